// round 8
// baseline (speedup 1.0000x reference)
#include <cuda_runtime.h>
#include <cstdint>

#define B_DIM 256
#define N_DIM 64
#define T_DIM 4096
#define H_DIM 16
#define TS    128   // t-tile per CTA
#define TILES 32    // CTAs per batch
#define SLOTS 9     // 9 slots x 32 CTAs = 288 CTAs (<= 296 co-resident)
#define SBC   136   // x SMEM row stride (floats): mod 32 = 8 -> conflict-free B frags
#define SW    68    // w SMEM row stride (floats)
#define XBUF  (N_DIM * SBC)   // floats per x buffer

// Scratch (device globals — no allocation allowed)
__device__ float2   g_part[B_DIM * TILES * N_DIM];  // per (b,tile,row): {sum,sumsq}
__device__ unsigned g_cnt[B_DIM];

// ======================= helpers =======================
__device__ __forceinline__ uint32_t smem_u32(const void* p) {
    uint32_t a;
    asm("{ .reg .u64 t; cvta.to.shared.u64 t, %1; cvt.u32.u64 %0, t; }" : "=r"(a) : "l"(p));
    return a;
}
__device__ __forceinline__ void cp16(uint32_t smem_dst, const void* gsrc) {
    asm volatile("cp.async.cg.shared.global [%0], [%1], 16;" :: "r"(smem_dst), "l"(gsrc) : "memory");
}
#define CP_COMMIT() asm volatile("cp.async.commit_group;" ::: "memory")
#define CP_WAIT(n)  asm volatile("cp.async.wait_group %0;" :: "n"(n) : "memory")

__device__ __forceinline__ unsigned ld_acq(const unsigned* p) {
    unsigned v;
    asm volatile("ld.acquire.gpu.global.u32 %0, [%1];" : "=r"(v) : "l"(p) : "memory");
    return v;
}
__device__ __forceinline__ uint32_t f2tf32(float f) {
    uint32_t r;
    asm("cvt.rna.tf32.f32 %0, %1;" : "=r"(r) : "f"(f));
    return r;
}
__device__ __forceinline__ void mma_tf32(float& d0, float& d1, float& d2, float& d3,
                                         uint32_t a0, uint32_t a1, uint32_t a2, uint32_t a3,
                                         uint32_t b0, uint32_t b1) {
    asm volatile(
        "mma.sync.aligned.m16n8k8.row.col.f32.tf32.tf32.f32 "
        "{%0,%1,%2,%3},{%4,%5,%6,%7},{%8,%9},{%0,%1,%2,%3};"
        : "+f"(d0), "+f"(d1), "+f"(d2), "+f"(d3)
        : "r"(a0), "r"(a1), "r"(a2), "r"(a3), "r"(b0), "r"(b1));
}

// ---------------------------------------------------------------------------
// Counter reset (runs first every launch; graph-replay safe).
// ---------------------------------------------------------------------------
__global__ void zero_kernel() {
    g_cnt[threadIdx.x] = 0u;
}

// ---------------------------------------------------------------------------
// Fused persistent kernel, double-buffered across batches.
// Grid = 288 CTAs (one co-resident wave). Slot s (32 CTAs = 32 t-tiles of
// 128) handles batches s, s+9, ... Per iteration: wait older buffer ->
// partial var sums -> publish+arrive -> spin for 32 siblings (NEXT batch's
// load is already in flight in the other buffer) -> energies + rank-1
// softmax in-SMEM -> tf32 GEMM + fp32 residual -> refill freed buffer with
// batch b+2*SLOTS. DRAM reads stay outstanding through every sync window.
// ---------------------------------------------------------------------------
__global__ __launch_bounds__(256, 2) void fused_kernel(const float* __restrict__ x,
                                                       const float* __restrict__ Wq,
                                                       const float* __restrict__ bq,
                                                       const float* __restrict__ Wk,
                                                       const float* __restrict__ bk,
                                                       float* __restrict__ out,
                                                       float* __restrict__ attn_out) {
    extern __shared__ float smem[];
    float* xs  = smem;                    // 2 x [64][SBC]
    float* ws  = smem + 2 * XBUF;         // [64][SW]
    float* e_s = ws + N_DIM * SW;         // [64]

    int slot = blockIdx.x >> 5;
    int tile = blockIdx.x & 31;
    int tid  = threadIdx.x;
    int wid  = tid >> 5;
    int lane = tid & 31;

    // Rank-1 logit coefficients (batch-independent).
    float c0 = 0.f, c1 = 0.f, c2 = 0.f, c3 = 0.f;
#pragma unroll
    for (int h = 0; h < H_DIM; h++) {
        float wq = __ldg(Wq + h), bqh = __ldg(bq + h);
        float wk = __ldg(Wk + h), bkh = __ldg(bk + h);
        c0 = fmaf(wq, wk, c0);
        c1 = fmaf(wq, bkh, c1);
        c2 = fmaf(bqh, wk, c2);
        c3 = fmaf(bqh, bkh, c3);
    }

    int ih = wid & 1;          // i half: rows [ih*32, +32)
    int tq = wid >> 1;         // t quarter: [tq*32, +32)
    int i0 = ih * 32;
    int r  = lane >> 2;        // 0..7
    int c  = lane & 3;         // 0..3

    const float* xtile = x + (size_t)tile * TS;  // + b*N*T per batch

    // Prologue: preload batches slot and slot+SLOTS into buffers 0,1.
#pragma unroll
    for (int p = 0; p < 2; p++) {
        int pb = slot + p * SLOTS;
        float* xc = xs + p * XBUF;
        const float* xg = xtile + (size_t)pb * N_DIM * T_DIM;
#pragma unroll
        for (int k = 0; k < 8; k++) {
            int f  = k * 256 + tid;   // float4 index; 32 per row
            int jj = f >> 5;
            int c4 = f & 31;
            cp16(smem_u32(xc + jj * SBC + c4 * 4),
                 xg + (size_t)jj * T_DIM + c4 * 4);
        }
        CP_COMMIT();
    }

    int it = 0;
    for (int b = slot; b < B_DIM; b += SLOTS, it++) {
        float* xc = xs + (it & 1) * XBUF;
        CP_WAIT(1);          // current buffer complete; next still loading
        __syncthreads();

        // ---- Phase 1: per-row partial sums over this tile's 128 t-cols ----
        {
            int j = tid >> 2, k = tid & 3;
            const float* base = xc + j * SBC + k * 32;
            float s = 0.f, ss = 0.f;
#pragma unroll
            for (int q = 0; q < 8; q++) {
                float4 v = *reinterpret_cast<const float4*>(base + q * 4);
                s  += (v.x + v.y) + (v.z + v.w);
                ss += v.x * v.x + v.y * v.y + v.z * v.z + v.w * v.w;
            }
            s  += __shfl_xor_sync(0xffffffffu, s, 1);
            ss += __shfl_xor_sync(0xffffffffu, ss, 1);
            s  += __shfl_xor_sync(0xffffffffu, s, 2);
            ss += __shfl_xor_sync(0xffffffffu, ss, 2);
            if (k == 0)
                g_part[(b * TILES + tile) * N_DIM + j] = make_float2(s, ss);
        }
        __threadfence();
        __syncthreads();
        if (tid == 0) atomicAdd(&g_cnt[b], 1u);

        // ---- Phase 2: wait for all 32 tiles (next batch load in flight) ----
        while (ld_acq(&g_cnt[b]) < (unsigned)TILES) __nanosleep(64);

        // ---- Phase 3: energies from reduced partials ----
        if (tid < 64) {
            const float2* pp = g_part + b * TILES * N_DIM;
            float s = 0.f, ss = 0.f;
#pragma unroll
            for (int t = 0; t < TILES; t++) {
                float2 p = pp[t * N_DIM + tid];
                s += p.x;
                ss += p.y;
            }
            float m = s * (1.f / T_DIM);
            e_s[tid] = fmaf(-m, m, ss * (1.f / T_DIM));
        }
        __syncthreads();

        // ---- Phase 4: rank-1 softmax weights into ws ----
        if (tid < 64) {
            const float scale = 0.25f;
            float ei = e_s[tid];
            float mx = -1e30f;
#pragma unroll
            for (int j = 0; j < N_DIM; j++) {
                float v = scale * (ei * e_s[j] * c0 + ei * c1 + e_s[j] * c2 + c3);
                if (j == tid) v = -1e9f;
                mx = fmaxf(mx, v);
            }
            float sum = 0.f;
#pragma unroll
            for (int j = 0; j < N_DIM; j++) {
                float v = scale * (ei * e_s[j] * c0 + ei * c1 + e_s[j] * c2 + c3);
                if (j == tid) v = -1e9f;
                float w = __expf(v - mx);
                ws[tid * SW + j] = w;
                sum += w;
            }
            float inv = 1.f / sum;
#pragma unroll
            for (int j = 0; j < N_DIM; j++)
                ws[tid * SW + j] *= inv;
        }
        __syncthreads();

        // Tile 0 writes attn_w output.
        if (tile == 0) {
            float* ao = attn_out + (size_t)b * N_DIM * N_DIM;
#pragma unroll
            for (int k = 0; k < 16; k++) {
                int f = tid * 16 + k;
                ao[f] = ws[(f >> 6) * SW + (f & 63)];
            }
        }

        // ---- Phase 5: A fragments (2 bands x 8 ksteps x 4 regs) ----
        uint32_t a[2][8][4];
#pragma unroll
        for (int band = 0; band < 2; band++) {
            int ib = i0 + band * 16;
#pragma unroll
            for (int ks = 0; ks < 8; ks++) {
                int j0 = ks * 8 + c;
                a[band][ks][0] = f2tf32(ws[(ib + r) * SW + j0]);
                a[band][ks][1] = f2tf32(ws[(ib + r + 8) * SW + j0]);
                a[band][ks][2] = f2tf32(ws[(ib + r) * SW + j0 + 4]);
                a[band][ks][3] = f2tf32(ws[(ib + r + 8) * SW + j0 + 4]);
            }
        }

        // ---- Phase 6: GEMM + residual from the SAME SMEM buffer ----
        float* ob = out + (size_t)b * N_DIM * T_DIM + (size_t)tile * TS;
#pragma unroll
        for (int nt = 0; nt < 4; nt++) {
            int t0 = tq * 32 + nt * 8;
            float d[2][4];
#pragma unroll
            for (int band = 0; band < 2; band++)
#pragma unroll
                for (int q = 0; q < 4; q++) d[band][q] = 0.f;
#pragma unroll
            for (int ks = 0; ks < 8; ks++) {
                uint32_t b0 = __float_as_uint(xc[(ks * 8 + c) * SBC + t0 + r]);
                uint32_t b1 = __float_as_uint(xc[(ks * 8 + c + 4) * SBC + t0 + r]);
                mma_tf32(d[0][0], d[0][1], d[0][2], d[0][3],
                         a[0][ks][0], a[0][ks][1], a[0][ks][2], a[0][ks][3], b0, b1);
                mma_tf32(d[1][0], d[1][1], d[1][2], d[1][3],
                         a[1][ks][0], a[1][ks][1], a[1][ks][2], a[1][ks][3], b0, b1);
            }
            int tcol = t0 + 2 * c;
#pragma unroll
            for (int band = 0; band < 2; band++) {
                int row0 = i0 + band * 16 + r, row1 = row0 + 8;
                float2 res0 = *reinterpret_cast<const float2*>(xc + row0 * SBC + tcol);
                float2 res1 = *reinterpret_cast<const float2*>(xc + row1 * SBC + tcol);
                float2 o0 = make_float2(d[band][0] + res0.x, d[band][1] + res0.y);
                float2 o1 = make_float2(d[band][2] + res1.x, d[band][3] + res1.y);
                *reinterpret_cast<float2*>(ob + (size_t)row0 * T_DIM + tcol) = o0;
                *reinterpret_cast<float2*>(ob + (size_t)row1 * T_DIM + tcol) = o1;
            }
        }
        __syncthreads();   // all warps done reading xc

        // ---- Refill freed buffer with batch b + 2*SLOTS ----
        {
            int nb = b + 2 * SLOTS;
            if (nb < B_DIM) {
                const float* xg = xtile + (size_t)nb * N_DIM * T_DIM;
#pragma unroll
                for (int k = 0; k < 8; k++) {
                    int f  = k * 256 + tid;
                    int jj = f >> 5;
                    int c4 = f & 31;
                    cp16(smem_u32(xc + jj * SBC + c4 * 4),
                         xg + (size_t)jj * T_DIM + c4 * 4);
                }
            }
            CP_COMMIT();   // unconditional: keeps wait_group accounting fixed
        }
    }
}

extern "C" void kernel_launch(void* const* d_in, const int* in_sizes, int n_in,
                              void* d_out, int out_size) {
    const float* x  = (const float*)d_in[0];
    const float* Wq = (const float*)d_in[1];
    const float* bq = (const float*)d_in[2];
    const float* Wk = (const float*)d_in[3];
    const float* bk = (const float*)d_in[4];

    float* out = (float*)d_out;
    float* attn_out = out + (size_t)B_DIM * N_DIM * T_DIM;

    const int smem_bytes = (2 * XBUF + N_DIM * SW + 64) * (int)sizeof(float);  // ~87.3 KB
    cudaFuncSetAttribute(fused_kernel, cudaFuncAttributeMaxDynamicSharedMemorySize, smem_bytes);

    zero_kernel<<<1, B_DIM>>>();
    fused_kernel<<<SLOTS * TILES, 256, smem_bytes>>>(x, Wq, bq, Wk, bk, out, attn_out);
}

// round 9
// speedup vs baseline: 1.4817x; 1.4817x over previous
#include <cuda_runtime.h>
#include <cstdint>

#define B_DIM 256
#define N_DIM 64
#define T_DIM 4096
#define H_DIM 16
#define TS    512   // t-tile per CTA (8 chunks)
#define CH    64    // t-chunk width
#define NCH   8     // chunks per tile
#define NBUF  4     // rotating chunk buffers
#define SBC   72    // x chunk SMEM row stride (floats): mod 32 = 8 -> conflict-free
#define SW    68    // w SMEM row stride (floats)

// Scratch (device global — no allocation allowed)
__device__ float g_energy[B_DIM * N_DIM];

// ======================= helpers =======================
__device__ __forceinline__ uint32_t smem_u32(const void* p) {
    uint32_t a;
    asm("{ .reg .u64 t; cvta.to.shared.u64 t, %1; cvt.u32.u64 %0, t; }" : "=r"(a) : "l"(p));
    return a;
}
__device__ __forceinline__ void cp16(uint32_t smem_dst, const void* gsrc) {
    asm volatile("cp.async.cg.shared.global [%0], [%1], 16;" :: "r"(smem_dst), "l"(gsrc) : "memory");
}
#define CP_COMMIT() asm volatile("cp.async.commit_group;" ::: "memory")
#define CP_WAIT(n)  asm volatile("cp.async.wait_group %0;" :: "n"(n) : "memory")

__device__ __forceinline__ uint32_t f2tf32(float f) {
    uint32_t r;
    asm("cvt.rna.tf32.f32 %0, %1;" : "=r"(r) : "f"(f));
    return r;
}
__device__ __forceinline__ void mma_tf32(float& d0, float& d1, float& d2, float& d3,
                                         uint32_t a0, uint32_t a1, uint32_t a2, uint32_t a3,
                                         uint32_t b0, uint32_t b1) {
    asm volatile(
        "mma.sync.aligned.m16n8k8.row.col.f32.tf32.tf32.f32 "
        "{%0,%1,%2,%3},{%4,%5,%6,%7},{%8,%9},{%0,%1,%2,%3};"
        : "+f"(d0), "+f"(d1), "+f"(d2), "+f"(d3)
        : "r"(a0), "r"(a1), "r"(a2), "r"(a3), "r"(b0), "r"(b1));
}

// ---------------------------------------------------------------------------
// Kernel 1: energy[b,n] = var(x[b,n,:]) over T. One warp per (b,n) row.
// ---------------------------------------------------------------------------
__global__ __launch_bounds__(256) void energy_kernel(const float* __restrict__ x) {
    int gw   = (blockIdx.x * blockDim.x + threadIdx.x) >> 5;
    int lane = threadIdx.x & 31;
    if (gw >= B_DIM * N_DIM) return;
    const float4* row = reinterpret_cast<const float4*>(x + (size_t)gw * T_DIM);
    float s = 0.f, ss = 0.f;
#pragma unroll
    for (int k = 0; k < 32; k++) {
        float4 v = row[k * 32 + lane];
        s  += (v.x + v.y) + (v.z + v.w);
        ss += v.x * v.x + v.y * v.y + v.z * v.z + v.w * v.w;
    }
#pragma unroll
    for (int o = 16; o > 0; o >>= 1) {
        s  += __shfl_xor_sync(0xffffffffu, s, o);
        ss += __shfl_xor_sync(0xffffffffu, ss, o);
    }
    if (lane == 0) {
        float m = s * (1.f / T_DIM);
        g_energy[gw] = fmaf(-m, m, ss * (1.f / T_DIM));
    }
}

// ---------------------------------------------------------------------------
// Kernel 2: attn weights (rank-1 logits + softmax) -> attn_out [b][i][j].
// ---------------------------------------------------------------------------
__global__ __launch_bounds__(64) void attn_kernel(const float* __restrict__ Wq,
                                                  const float* __restrict__ bq,
                                                  const float* __restrict__ Wk,
                                                  const float* __restrict__ bk,
                                                  float* __restrict__ attn_out) {
    __shared__ float e[N_DIM];
    __shared__ float wsm[N_DIM * 65];
    int b = blockIdx.x;
    int i = threadIdx.x;
    e[i] = g_energy[b * N_DIM + i];

    float c0 = 0.f, c1 = 0.f, c2 = 0.f, c3 = 0.f;
#pragma unroll
    for (int h = 0; h < H_DIM; h++) {
        float wq = Wq[h], bqh = bq[h], wk = Wk[h], bkh = bk[h];
        c0 = fmaf(wq, wk, c0);
        c1 = fmaf(wq, bkh, c1);
        c2 = fmaf(bqh, wk, c2);
        c3 = fmaf(bqh, bkh, c3);
    }
    __syncthreads();

    const float scale = 0.25f;
    float ei = e[i];
    float l[N_DIM];
    float mx = -1e30f;
#pragma unroll
    for (int j = 0; j < N_DIM; j++) {
        float ej = e[j];
        float v = scale * (ei * ej * c0 + ei * c1 + ej * c2 + c3);
        if (j == i) v = -1e9f;
        l[j] = v;
        mx = fmaxf(mx, v);
    }
    float sum = 0.f;
#pragma unroll
    for (int j = 0; j < N_DIM; j++) {
        float w = __expf(l[j] - mx);
        l[j] = w;
        sum += w;
    }
    float inv = 1.f / sum;
#pragma unroll
    for (int j = 0; j < N_DIM; j++)
        wsm[i * 65 + j] = l[j] * inv;
    __syncthreads();

    float* ao = attn_out + (size_t)b * N_DIM * N_DIM;
#pragma unroll
    for (int k = 0; k < N_DIM; k++)
        ao[k * 64 + i] = wsm[k * 65 + i];  // w[k][i], coalesced
}

// ---------------------------------------------------------------------------
// Kernel 3: out[b,i,t] = sum_j w[b,i,j]*x[b,j,t] + x[b,i,t]
// CTA: (t-tile 512, batch). 8 chunks [64 j][64 t] streamed through 4 rotating
// cp.async buffers (sustained prefetch depth 4). B fragments raw fp32 bits
// (tf32 HW truncation); residual exact fp32 from the same SMEM. 8 warps =
// 2 i-halves x 4 t-quarters (16 t per warp per chunk).
// ---------------------------------------------------------------------------
__global__ __launch_bounds__(256, 2) void out_kernel(const float* __restrict__ x,
                                                     const float* __restrict__ w,
                                                     float* __restrict__ out) {
    extern __shared__ float smem[];
    float* xs = smem;                          // NBUF x [64][SBC]
    float* ws = smem + NBUF * N_DIM * SBC;     // [64][SW]

    int b    = blockIdx.y;
    int tile = blockIdx.x;
    int tid  = threadIdx.x;
    int wid  = tid >> 5;
    int lane = tid & 31;

    const float* xb = x + (size_t)b * N_DIM * T_DIM + (size_t)tile * TS;
    const float* wsrc = w + (size_t)b * N_DIM * N_DIM;

    // Group 0: w — 64x64 floats = 1024 float4, 4 per thread (16 float4/row).
#pragma unroll
    for (int k = 0; k < 4; k++) {
        int f  = k * 256 + tid;   // float4 index
        int i  = f >> 4;          // row (16 float4 per row)
        int c4 = f & 15;
        cp16(smem_u32(ws + i * SW + c4 * 4), wsrc + f * 4);
    }
    CP_COMMIT();
    // Groups 1..4: first NBUF chunks (each 64 rows x 16 float4; 4 per thread).
#pragma unroll
    for (int ch = 0; ch < NBUF; ch++) {
        float* xc = xs + ch * N_DIM * SBC;
#pragma unroll
        for (int k = 0; k < 4; k++) {
            int f  = k * 256 + tid;
            int j  = f >> 4;
            int c4 = f & 15;
            cp16(smem_u32(xc + j * SBC + c4 * 4),
                 xb + (size_t)j * T_DIM + ch * CH + c4 * 4);
        }
        CP_COMMIT();
    }

    int ih = wid & 1;          // i half: rows [ih*32, +32)
    int tq = wid >> 1;         // t quarter within chunk: [tq*16, +16)
    int i0 = ih * 32;
    int r  = lane >> 2;        // 0..7
    int c  = lane & 3;         // 0..3

    // Wait for w (NBUF chunk groups may remain pending), build A fragments.
    CP_WAIT(NBUF);
    __syncthreads();
    uint32_t a[2][8][4];
#pragma unroll
    for (int band = 0; band < 2; band++) {
        int ib = i0 + band * 16;
#pragma unroll
        for (int ks = 0; ks < 8; ks++) {
            int j0 = ks * 8 + c;
            a[band][ks][0] = f2tf32(ws[(ib + r) * SW + j0]);
            a[band][ks][1] = f2tf32(ws[(ib + r + 8) * SW + j0]);
            a[band][ks][2] = f2tf32(ws[(ib + r) * SW + j0 + 4]);
            a[band][ks][3] = f2tf32(ws[(ib + r + 8) * SW + j0 + 4]);
        }
    }

    float* ob = out + (size_t)b * N_DIM * T_DIM + (size_t)tile * TS;

#pragma unroll
    for (int ch = 0; ch < NCH; ch++) {
        // Chunk ch done when <= NBUF-1 newer groups pending.
        CP_WAIT(NBUF - 1);
        __syncthreads();

        const float* xc = xs + (ch & (NBUF - 1)) * N_DIM * SBC;
#pragma unroll
        for (int nt = 0; nt < 2; nt++) {
            int t0 = tq * 16 + nt * 8;
            float d[2][4];
#pragma unroll
            for (int band = 0; band < 2; band++)
#pragma unroll
                for (int q = 0; q < 4; q++) d[band][q] = 0.f;
#pragma unroll
            for (int ks = 0; ks < 8; ks++) {
                // Raw fp32 bits -> tf32 truncation in HW.
                uint32_t b0 = __float_as_uint(xc[(ks * 8 + c) * SBC + t0 + r]);
                uint32_t b1 = __float_as_uint(xc[(ks * 8 + c + 4) * SBC + t0 + r]);
                mma_tf32(d[0][0], d[0][1], d[0][2], d[0][3],
                         a[0][ks][0], a[0][ks][1], a[0][ks][2], a[0][ks][3], b0, b1);
                mma_tf32(d[1][0], d[1][1], d[1][2], d[1][3],
                         a[1][ks][0], a[1][ks][1], a[1][ks][2], a[1][ks][3], b0, b1);
            }
            // Epilogue: exact fp32 residual + coalesced STG.64.
            int tcol = t0 + 2 * c;
#pragma unroll
            for (int band = 0; band < 2; band++) {
                int row0 = i0 + band * 16 + r, row1 = row0 + 8;
                float2 res0 = *reinterpret_cast<const float2*>(xc + row0 * SBC + tcol);
                float2 res1 = *reinterpret_cast<const float2*>(xc + row1 * SBC + tcol);
                float2 o0 = make_float2(d[band][0] + res0.x, d[band][1] + res0.y);
                float2 o1 = make_float2(d[band][2] + res1.x, d[band][3] + res1.y);
                int tg = ch * CH + tcol;
                *reinterpret_cast<float2*>(ob + (size_t)row0 * T_DIM + tg) = o0;
                *reinterpret_cast<float2*>(ob + (size_t)row1 * T_DIM + tg) = o1;
            }
        }
        __syncthreads();   // all warps done reading buffer (ch & 3)

        // Refill this buffer with chunk ch+NBUF (empty commit keeps counts).
        int nch = ch + NBUF;
        if (nch < NCH) {
            float* xc2 = xs + (ch & (NBUF - 1)) * N_DIM * SBC;
#pragma unroll
            for (int k = 0; k < 4; k++) {
                int f  = k * 256 + tid;
                int j  = f >> 4;
                int c4 = f & 15;
                cp16(smem_u32(xc2 + j * SBC + c4 * 4),
                     xb + (size_t)j * T_DIM + nch * CH + c4 * 4);
            }
        }
        CP_COMMIT();
    }
}

extern "C" void kernel_launch(void* const* d_in, const int* in_sizes, int n_in,
                              void* d_out, int out_size) {
    const float* x  = (const float*)d_in[0];
    const float* Wq = (const float*)d_in[1];
    const float* bq = (const float*)d_in[2];
    const float* Wk = (const float*)d_in[3];
    const float* bk = (const float*)d_in[4];

    float* out = (float*)d_out;
    float* attn_out = out + (size_t)B_DIM * N_DIM * T_DIM;

    const int smem_bytes = (NBUF * N_DIM * SBC + N_DIM * SW) * (int)sizeof(float);  // 91136
    cudaFuncSetAttribute(out_kernel, cudaFuncAttributeMaxDynamicSharedMemorySize, smem_bytes);

    energy_kernel<<<(B_DIM * N_DIM * 32) / 256, 256>>>(x);
    attn_kernel<<<B_DIM, 64>>>(Wq, bq, Wk, bk, attn_out);
    dim3 grid(T_DIM / TS, B_DIM);
    out_kernel<<<grid, 256, smem_bytes>>>(x, attn_out, out);
}

// round 10
// speedup vs baseline: 1.5609x; 1.0535x over previous
#include <cuda_runtime.h>
#include <cstdint>

#define B_DIM 256
#define N_DIM 64
#define T_DIM 4096
#define H_DIM 16
#define TS    256   // t-tile per out CTA
#define CH    64    // t-chunk width (4 chunks per tile)
#define SBC   72    // x chunk SMEM row stride (floats): mod 32 = 8 -> conflict-free
#define SW    68    // w SMEM row stride (floats)
#define GRP   32    // batches per group
#define NGRP  8     // groups
#define O_CTAS (GRP * 16)        // 512 out CTAs per launch (16 t-tiles per batch)
#define E_CTAS (GRP * N_DIM / 8) // 256 energy CTAs per launch (8 rows per CTA)

// Scratch (device global — no allocation allowed)
__device__ float g_energy[B_DIM * N_DIM];

// ======================= helpers =======================
__device__ __forceinline__ uint32_t smem_u32(const void* p) {
    uint32_t a;
    asm("{ .reg .u64 t; cvta.to.shared.u64 t, %1; cvt.u32.u64 %0, t; }" : "=r"(a) : "l"(p));
    return a;
}
__device__ __forceinline__ void cp16(uint32_t smem_dst, const void* gsrc) {
    asm volatile("cp.async.cg.shared.global [%0], [%1], 16;" :: "r"(smem_dst), "l"(gsrc) : "memory");
}
#define CP_COMMIT() asm volatile("cp.async.commit_group;" ::: "memory")
#define CP_WAIT(n)  asm volatile("cp.async.wait_group %0;" :: "n"(n) : "memory")

__device__ __forceinline__ uint32_t f2tf32(float f) {
    uint32_t r;
    asm("cvt.rna.tf32.f32 %0, %1;" : "=r"(r) : "f"(f));
    return r;
}
__device__ __forceinline__ void mma_tf32(float& d0, float& d1, float& d2, float& d3,
                                         uint32_t a0, uint32_t a1, uint32_t a2, uint32_t a3,
                                         uint32_t b0, uint32_t b1) {
    asm volatile(
        "mma.sync.aligned.m16n8k8.row.col.f32.tf32.tf32.f32 "
        "{%0,%1,%2,%3},{%4,%5,%6,%7},{%8,%9},{%0,%1,%2,%3};"
        : "+f"(d0), "+f"(d1), "+f"(d2), "+f"(d3)
        : "r"(a0), "r"(a1), "r"(a2), "r"(a3), "r"(b0), "r"(b1));
}

// ---------------------------------------------------------------------------
// Mega-kernel, launched NGRP+1 times (step = 0..NGRP).
//   blockIdx >= O_CTAS: ENERGY path for group `step`   (skipped at step==NGRP)
//   blockIdx <  O_CTAS: OUT path for group `step-1`    (skipped at step==0)
// Energy CTAs stream group `step`'s x from DRAM into L2; out CTAs re-read
// group `step-1`'s x (L2-hot from the previous launch) and write out.
// The rank-1 softmax is computed redundantly per out-CTA from g_energy,
// overlapped with the cp.async prefetch; tile 0 writes attn_w.
// ---------------------------------------------------------------------------
__global__ __launch_bounds__(256, 2) void mega_kernel(const float* __restrict__ x,
                                                      const float* __restrict__ Wq,
                                                      const float* __restrict__ bq,
                                                      const float* __restrict__ Wk,
                                                      const float* __restrict__ bk,
                                                      float* __restrict__ out,
                                                      float* __restrict__ attn_out,
                                                      int step) {
    int tid  = threadIdx.x;
    int wid  = tid >> 5;
    int lane = tid & 31;

    // ===================== ENERGY path =====================
    if (blockIdx.x >= O_CTAS) {
        if (step >= NGRP) return;
        int gw = step * GRP * N_DIM + (int)(blockIdx.x - O_CTAS) * 8 + wid;
        const float4* row = reinterpret_cast<const float4*>(x + (size_t)gw * T_DIM);
        float s = 0.f, ss = 0.f;
#pragma unroll
        for (int k = 0; k < 32; k++) {
            float4 v = row[k * 32 + lane];
            s  += (v.x + v.y) + (v.z + v.w);
            ss += v.x * v.x + v.y * v.y + v.z * v.z + v.w * v.w;
        }
#pragma unroll
        for (int o = 16; o > 0; o >>= 1) {
            s  += __shfl_xor_sync(0xffffffffu, s, o);
            ss += __shfl_xor_sync(0xffffffffu, ss, o);
        }
        if (lane == 0) {
            float m = s * (1.f / T_DIM);
            g_energy[gw] = fmaf(-m, m, ss * (1.f / T_DIM));
        }
        return;
    }

    // ===================== OUT path =====================
    if (step == 0) return;
    extern __shared__ float smem[];
    float* xs  = smem;                       // 4 x [64][SBC]
    float* ws  = smem + 4 * N_DIM * SBC;     // [64][SW]
    float* e_s = ws + N_DIM * SW;            // [64]

    int go   = step - 1;
    int b    = go * GRP + ((int)blockIdx.x >> 4);
    int tile = blockIdx.x & 15;

    const float* xb = x + (size_t)b * N_DIM * T_DIM + (size_t)tile * TS;

    // Prefetch all 4 x chunks (groups 1..4), 4 cp16 per thread per chunk.
#pragma unroll
    for (int ch = 0; ch < 4; ch++) {
        float* xc = xs + ch * N_DIM * SBC;
#pragma unroll
        for (int k = 0; k < 4; k++) {
            int f  = k * 256 + tid;
            int j  = f >> 4;
            int c4 = f & 15;
            cp16(smem_u32(xc + j * SBC + c4 * 4),
                 xb + (size_t)j * T_DIM + ch * CH + c4 * 4);
        }
        CP_COMMIT();
    }

    // In-CTA softmax (overlaps the cp.async prefetch).
    if (tid < 64) e_s[tid] = g_energy[b * N_DIM + tid];
    __syncthreads();
    if (tid < 64) {
        float c0 = 0.f, c1 = 0.f, c2 = 0.f, c3 = 0.f;
#pragma unroll
        for (int h = 0; h < H_DIM; h++) {
            float wq = __ldg(Wq + h), bqh = __ldg(bq + h);
            float wk = __ldg(Wk + h), bkh = __ldg(bk + h);
            c0 = fmaf(wq, wk, c0);
            c1 = fmaf(wq, bkh, c1);
            c2 = fmaf(bqh, wk, c2);
            c3 = fmaf(bqh, bkh, c3);
        }
        const float scale = 0.25f;
        float ei = e_s[tid];
        float mx = -1e30f;
#pragma unroll
        for (int j = 0; j < N_DIM; j++) {
            float v = scale * (ei * e_s[j] * c0 + ei * c1 + e_s[j] * c2 + c3);
            if (j == tid) v = -1e9f;
            mx = fmaxf(mx, v);
        }
        float sum = 0.f;
#pragma unroll
        for (int j = 0; j < N_DIM; j++) {
            float v = scale * (ei * e_s[j] * c0 + ei * c1 + e_s[j] * c2 + c3);
            if (j == tid) v = -1e9f;
            float wv = __expf(v - mx);
            ws[tid * SW + j] = wv;
            sum += wv;
        }
        float inv = 1.f / sum;
#pragma unroll
        for (int j = 0; j < N_DIM; j++)
            ws[tid * SW + j] *= inv;
    }
    __syncthreads();

    // Tile 0 writes attn_w for this batch.
    if (tile == 0) {
        float* ao = attn_out + (size_t)b * N_DIM * N_DIM;
#pragma unroll
        for (int k = 0; k < 16; k++) {
            int f = tid * 16 + k;
            ao[f] = ws[(f >> 6) * SW + (f & 63)];
        }
    }

    int ih = wid & 1;          // i half: rows [ih*32, +32)
    int tq = wid >> 1;         // t quarter within chunk: [tq*16, +16)
    int i0 = ih * 32;
    int r  = lane >> 2;        // 0..7
    int c  = lane & 3;         // 0..3

    // A fragments (2 bands x 8 ksteps x 4 regs, rna cvt).
    uint32_t a[2][8][4];
#pragma unroll
    for (int band = 0; band < 2; band++) {
        int ib = i0 + band * 16;
#pragma unroll
        for (int ks = 0; ks < 8; ks++) {
            int j0 = ks * 8 + c;
            a[band][ks][0] = f2tf32(ws[(ib + r) * SW + j0]);
            a[band][ks][1] = f2tf32(ws[(ib + r + 8) * SW + j0]);
            a[band][ks][2] = f2tf32(ws[(ib + r) * SW + j0 + 4]);
            a[band][ks][3] = f2tf32(ws[(ib + r + 8) * SW + j0 + 4]);
        }
    }

    float* ob = out + (size_t)b * N_DIM * T_DIM + (size_t)tile * TS;

#pragma unroll
    for (int ch = 0; ch < 4; ch++) {
        if (ch == 0) CP_WAIT(3);
        else if (ch == 1) CP_WAIT(2);
        else if (ch == 2) CP_WAIT(1);
        else CP_WAIT(0);
        __syncthreads();

        const float* xc = xs + ch * N_DIM * SBC;
#pragma unroll
        for (int nt = 0; nt < 2; nt++) {
            int t0 = tq * 16 + nt * 8;
            float d[2][4];
#pragma unroll
            for (int band = 0; band < 2; band++)
#pragma unroll
                for (int q = 0; q < 4; q++) d[band][q] = 0.f;
#pragma unroll
            for (int ks = 0; ks < 8; ks++) {
                // Raw fp32 bits -> tf32 truncation in HW.
                uint32_t b0 = __float_as_uint(xc[(ks * 8 + c) * SBC + t0 + r]);
                uint32_t b1 = __float_as_uint(xc[(ks * 8 + c + 4) * SBC + t0 + r]);
                mma_tf32(d[0][0], d[0][1], d[0][2], d[0][3],
                         a[0][ks][0], a[0][ks][1], a[0][ks][2], a[0][ks][3], b0, b1);
                mma_tf32(d[1][0], d[1][1], d[1][2], d[1][3],
                         a[1][ks][0], a[1][ks][1], a[1][ks][2], a[1][ks][3], b0, b1);
            }
            // Epilogue: exact fp32 residual + coalesced STG.64.
            int tcol = t0 + 2 * c;
#pragma unroll
            for (int band = 0; band < 2; band++) {
                int row0 = i0 + band * 16 + r, row1 = row0 + 8;
                float2 res0 = *reinterpret_cast<const float2*>(xc + row0 * SBC + tcol);
                float2 res1 = *reinterpret_cast<const float2*>(xc + row1 * SBC + tcol);
                float2 o0 = make_float2(d[band][0] + res0.x, d[band][1] + res0.y);
                float2 o1 = make_float2(d[band][2] + res1.x, d[band][3] + res1.y);
                int tg = ch * CH + tcol;
                *reinterpret_cast<float2*>(ob + (size_t)row0 * T_DIM + tg) = o0;
                *reinterpret_cast<float2*>(ob + (size_t)row1 * T_DIM + tg) = o1;
            }
        }
    }
}

extern "C" void kernel_launch(void* const* d_in, const int* in_sizes, int n_in,
                              void* d_out, int out_size) {
    const float* x  = (const float*)d_in[0];
    const float* Wq = (const float*)d_in[1];
    const float* bq = (const float*)d_in[2];
    const float* Wk = (const float*)d_in[3];
    const float* bk = (const float*)d_in[4];

    float* out = (float*)d_out;
    float* attn_out = out + (size_t)B_DIM * N_DIM * T_DIM;

    const int smem_bytes = (4 * N_DIM * SBC + N_DIM * SW + 64) * (int)sizeof(float);  // 91392
    cudaFuncSetAttribute(mega_kernel, cudaFuncAttributeMaxDynamicSharedMemorySize, smem_bytes);

    for (int step = 0; step <= NGRP; step++) {
        mega_kernel<<<O_CTAS + E_CTAS, 256, smem_bytes>>>(
            x, Wq, bq, Wk, bk, out, attn_out, step);
    }
}

// round 11
// speedup vs baseline: 1.7698x; 1.1338x over previous
#include <cuda_runtime.h>
#include <cstdint>

#define B_DIM 256
#define N_DIM 64
#define T_DIM 4096
#define H_DIM 16
#define TS    256   // t-tile per CTA
#define CH    64    // t-chunk width (4 chunks per tile)
#define SBC   72    // x chunk SMEM row stride (floats): mod 32 = 8 -> conflict-free
#define SW    68    // w SMEM row stride (floats)

// Scratch (device global — no allocation allowed)
__device__ float g_energy[B_DIM * N_DIM];

// ======================= helpers =======================
__device__ __forceinline__ uint32_t smem_u32(const void* p) {
    uint32_t a;
    asm("{ .reg .u64 t; cvta.to.shared.u64 t, %1; cvt.u32.u64 %0, t; }" : "=r"(a) : "l"(p));
    return a;
}
__device__ __forceinline__ void cp16(uint32_t smem_dst, const void* gsrc) {
    asm volatile("cp.async.cg.shared.global [%0], [%1], 16;" :: "r"(smem_dst), "l"(gsrc) : "memory");
}
#define CP_COMMIT() asm volatile("cp.async.commit_group;" ::: "memory")
#define CP_WAIT(n)  asm volatile("cp.async.wait_group %0;" :: "n"(n) : "memory")

__device__ __forceinline__ uint32_t f2tf32(float f) {
    uint32_t r;
    asm("cvt.rna.tf32.f32 %0, %1;" : "=r"(r) : "f"(f));
    return r;
}
__device__ __forceinline__ void mma_tf32(float& d0, float& d1, float& d2, float& d3,
                                         uint32_t a0, uint32_t a1, uint32_t a2, uint32_t a3,
                                         uint32_t b0, uint32_t b1) {
    asm volatile(
        "mma.sync.aligned.m16n8k8.row.col.f32.tf32.tf32.f32 "
        "{%0,%1,%2,%3},{%4,%5,%6,%7},{%8,%9},{%0,%1,%2,%3};"
        : "+f"(d0), "+f"(d1), "+f"(d2), "+f"(d3)
        : "r"(a0), "r"(a1), "r"(a2), "r"(a3), "r"(b0), "r"(b1));
}

// ---------------------------------------------------------------------------
// Kernel 1: energy[b,n] = var(x[b,n,:]) over T. One warp per (b,n) row.
// Processes batches in ASCENDING order -> tail batches stay hot in L2 for
// out_kernel (which runs in DESCENDING order).
// ---------------------------------------------------------------------------
__global__ __launch_bounds__(256) void energy_kernel(const float* __restrict__ x) {
    int gw   = (blockIdx.x * blockDim.x + threadIdx.x) >> 5;
    int lane = threadIdx.x & 31;
    if (gw >= B_DIM * N_DIM) return;
    const float4* row = reinterpret_cast<const float4*>(x + (size_t)gw * T_DIM);
    float s = 0.f, ss = 0.f;
#pragma unroll
    for (int k = 0; k < 32; k++) {
        float4 v = row[k * 32 + lane];
        s  += (v.x + v.y) + (v.z + v.w);
        ss += v.x * v.x + v.y * v.y + v.z * v.z + v.w * v.w;
    }
#pragma unroll
    for (int o = 16; o > 0; o >>= 1) {
        s  += __shfl_xor_sync(0xffffffffu, s, o);
        ss += __shfl_xor_sync(0xffffffffu, ss, o);
    }
    if (lane == 0) {
        float m = s * (1.f / T_DIM);
        g_energy[gw] = fmaf(-m, m, ss * (1.f / T_DIM));
    }
}

// ---------------------------------------------------------------------------
// Kernel 2: out[b,i,t] = sum_j w[b,i,j]*x[b,j,t] + x[b,i,t], with the rank-1
// softmax computed in-CTA from g_energy (overlapped with cp.async prefetch).
// Batches processed in REVERSE order so early CTAs hit the L2-resident tail
// of x left by energy_kernel. Tile 0 of each batch writes attn_w.
// CTA: (t-tile 256). 4 chunk buffers, loads issued up-front. B fragments are
// raw fp32 bits (tf32 HW truncation); residual exact fp32 from same SMEM.
// ---------------------------------------------------------------------------
__global__ __launch_bounds__(256, 2) void out_kernel(const float* __restrict__ x,
                                                     const float* __restrict__ Wq,
                                                     const float* __restrict__ bq,
                                                     const float* __restrict__ Wk,
                                                     const float* __restrict__ bk,
                                                     float* __restrict__ out,
                                                     float* __restrict__ attn_out) {
    extern __shared__ float smem[];
    float* xs  = smem;                       // 4 x [64][SBC]
    float* ws  = smem + 4 * N_DIM * SBC;     // [64][SW]
    float* e_s = ws + N_DIM * SW;            // [64]

    int b    = B_DIM - 1 - (int)blockIdx.y;  // reverse batch order (L2 reuse)
    int tile = blockIdx.x;
    int tid  = threadIdx.x;
    int wid  = tid >> 5;
    int lane = tid & 31;

    const float* xb = x + (size_t)b * N_DIM * T_DIM + (size_t)tile * TS;

    // Prefetch all 4 x chunks (groups 1..4), 4 cp16 per thread per chunk.
#pragma unroll
    for (int ch = 0; ch < 4; ch++) {
        float* xc = xs + ch * N_DIM * SBC;
#pragma unroll
        for (int k = 0; k < 4; k++) {
            int f  = k * 256 + tid;
            int j  = f >> 4;
            int c4 = f & 15;
            cp16(smem_u32(xc + j * SBC + c4 * 4),
                 xb + (size_t)j * T_DIM + ch * CH + c4 * 4);
        }
        CP_COMMIT();
    }

    // In-CTA rank-1 softmax (overlaps the cp.async prefetch).
    if (tid < 64) e_s[tid] = g_energy[b * N_DIM + tid];
    __syncthreads();
    if (tid < 64) {
        float c0 = 0.f, c1 = 0.f, c2 = 0.f, c3 = 0.f;
#pragma unroll
        for (int h = 0; h < H_DIM; h++) {
            float wq = __ldg(Wq + h), bqh = __ldg(bq + h);
            float wk = __ldg(Wk + h), bkh = __ldg(bk + h);
            c0 = fmaf(wq, wk, c0);
            c1 = fmaf(wq, bkh, c1);
            c2 = fmaf(bqh, wk, c2);
            c3 = fmaf(bqh, bkh, c3);
        }
        const float scale = 0.25f;
        float ei = e_s[tid];
        float mx = -1e30f;
#pragma unroll
        for (int j = 0; j < N_DIM; j++) {
            float v = scale * (ei * e_s[j] * c0 + ei * c1 + e_s[j] * c2 + c3);
            if (j == tid) v = -1e9f;
            mx = fmaxf(mx, v);
        }
        float sum = 0.f;
#pragma unroll
        for (int j = 0; j < N_DIM; j++) {
            float v = scale * (ei * e_s[j] * c0 + ei * c1 + e_s[j] * c2 + c3);
            if (j == tid) v = -1e9f;
            float wv = __expf(v - mx);
            ws[tid * SW + j] = wv;
            sum += wv;
        }
        float inv = 1.f / sum;
#pragma unroll
        for (int j = 0; j < N_DIM; j++)
            ws[tid * SW + j] *= inv;
    }
    __syncthreads();

    // Tile 0 writes attn_w for this batch (coalesced-ish, 16 floats/thread).
    if (tile == 0) {
        float* ao = attn_out + (size_t)b * N_DIM * N_DIM;
#pragma unroll
        for (int k = 0; k < 16; k++) {
            int f = tid * 16 + k;
            ao[f] = ws[(f >> 6) * SW + (f & 63)];
        }
    }

    int ih = wid & 1;          // i half: rows [ih*32, +32)
    int tq = wid >> 1;         // t quarter within chunk: [tq*16, +16)
    int i0 = ih * 32;
    int r  = lane >> 2;        // 0..7
    int c  = lane & 3;         // 0..3

    // A fragments (2 bands x 8 ksteps x 4 regs, rna cvt).
    uint32_t a[2][8][4];
#pragma unroll
    for (int band = 0; band < 2; band++) {
        int ib = i0 + band * 16;
#pragma unroll
        for (int ks = 0; ks < 8; ks++) {
            int j0 = ks * 8 + c;
            a[band][ks][0] = f2tf32(ws[(ib + r) * SW + j0]);
            a[band][ks][1] = f2tf32(ws[(ib + r + 8) * SW + j0]);
            a[band][ks][2] = f2tf32(ws[(ib + r) * SW + j0 + 4]);
            a[band][ks][3] = f2tf32(ws[(ib + r + 8) * SW + j0 + 4]);
        }
    }

    float* ob = out + (size_t)b * N_DIM * T_DIM + (size_t)tile * TS;

#pragma unroll
    for (int ch = 0; ch < 4; ch++) {
        if (ch == 0) CP_WAIT(3);
        else if (ch == 1) CP_WAIT(2);
        else if (ch == 2) CP_WAIT(1);
        else CP_WAIT(0);
        __syncthreads();

        const float* xc = xs + ch * N_DIM * SBC;
#pragma unroll
        for (int nt = 0; nt < 2; nt++) {
            int t0 = tq * 16 + nt * 8;
            float d[2][4];
#pragma unroll
            for (int band = 0; band < 2; band++)
#pragma unroll
                for (int q = 0; q < 4; q++) d[band][q] = 0.f;
#pragma unroll
            for (int ks = 0; ks < 8; ks++) {
                // Raw fp32 bits -> tf32 truncation in HW.
                uint32_t b0 = __float_as_uint(xc[(ks * 8 + c) * SBC + t0 + r]);
                uint32_t b1 = __float_as_uint(xc[(ks * 8 + c + 4) * SBC + t0 + r]);
                mma_tf32(d[0][0], d[0][1], d[0][2], d[0][3],
                         a[0][ks][0], a[0][ks][1], a[0][ks][2], a[0][ks][3], b0, b1);
                mma_tf32(d[1][0], d[1][1], d[1][2], d[1][3],
                         a[1][ks][0], a[1][ks][1], a[1][ks][2], a[1][ks][3], b0, b1);
            }
            // Epilogue: exact fp32 residual + coalesced STG.64.
            int tcol = t0 + 2 * c;
#pragma unroll
            for (int band = 0; band < 2; band++) {
                int row0 = i0 + band * 16 + r, row1 = row0 + 8;
                float2 res0 = *reinterpret_cast<const float2*>(xc + row0 * SBC + tcol);
                float2 res1 = *reinterpret_cast<const float2*>(xc + row1 * SBC + tcol);
                float2 o0 = make_float2(d[band][0] + res0.x, d[band][1] + res0.y);
                float2 o1 = make_float2(d[band][2] + res1.x, d[band][3] + res1.y);
                int tg = ch * CH + tcol;
                *reinterpret_cast<float2*>(ob + (size_t)row0 * T_DIM + tg) = o0;
                *reinterpret_cast<float2*>(ob + (size_t)row1 * T_DIM + tg) = o1;
            }
        }
    }
}

extern "C" void kernel_launch(void* const* d_in, const int* in_sizes, int n_in,
                              void* d_out, int out_size) {
    const float* x  = (const float*)d_in[0];
    const float* Wq = (const float*)d_in[1];
    const float* bq = (const float*)d_in[2];
    const float* Wk = (const float*)d_in[3];
    const float* bk = (const float*)d_in[4];

    float* out = (float*)d_out;
    float* attn_out = out + (size_t)B_DIM * N_DIM * T_DIM;

    const int smem_bytes = (4 * N_DIM * SBC + N_DIM * SW + 64) * (int)sizeof(float);  // 91392
    cudaFuncSetAttribute(out_kernel, cudaFuncAttributeMaxDynamicSharedMemorySize, smem_bytes);

    energy_kernel<<<(B_DIM * N_DIM * 32) / 256, 256>>>(x);
    dim3 grid(T_DIM / TS, B_DIM);
    out_kernel<<<grid, 256, smem_bytes>>>(x, Wq, bq, Wk, bk, out, attn_out);
}